// round 4
// baseline (speedup 1.0000x reference)
#include <cuda_runtime.h>
#include <math.h>

#define BNUM   2
#define SLEN   2048
#define DMODEL 1024
#define NH     16
#define HD     64
#define MTOT   (BNUM * SLEN)   // 4096

// Scratch (static device globals -- allocation-free)
__device__ float g_q[BNUM * NH * SLEN * HD];   // [b][h][s][dh]
__device__ float g_k[BNUM * NH * SLEN * HD];
__device__ float g_v[BNUM * NH * SLEN * HD];
__device__ float g_o[MTOT * DMODEL];           // [b*s][d] attention output

// ---------------------------------------------------------------------------
// QKV projection + fused RoPE.
// C[m][n] = sum_k x[m][k] * W[n][k], scattered to [b][h][s][dh]; RoPE on q,k.
// Tiles: BM=128, BN=64, BK=16; 256 threads; 8x4 microtile.
// As: [k=16][m=128] stride 132 (reg-transposed store, conflict-free)
// Bs: [k=16][n=64]  stride 68
// ---------------------------------------------------------------------------
__global__ __launch_bounds__(256) void qkv_proj_kernel(
    const float* __restrict__ x,
    const float* __restrict__ Wq,
    const float* __restrict__ Wk,
    const float* __restrict__ Wv)
{
    __shared__ float As[16 * 132];
    __shared__ float Bs[16 * 68];

    const int z = blockIdx.z;                    // 0=q 1=k 2=v
    const float* __restrict__ W = (z == 0) ? Wq : ((z == 1) ? Wk : Wv);
    float* __restrict__ Out     = (z == 0) ? g_q : ((z == 1) ? g_k : g_v);

    const int m0 = blockIdx.x * 128;
    const int n0 = blockIdx.y * 64;
    const int tid = threadIdx.x;
    const int tx = tid & 15, ty = tid >> 4;      // compute layout 16x16
    const int lk = tid & 15, lg = tid >> 4;      // loader layout

    float acc[8][4];
#pragma unroll
    for (int i = 0; i < 8; ++i)
#pragma unroll
        for (int j = 0; j < 4; ++j) acc[i][j] = 0.f;

    for (int kt = 0; kt < DMODEL; kt += 16) {
        // A tile: rows m0+4*grp+j, col kt+lk  -> As[k][m] (transposed via regs)
#pragma unroll
        for (int h2 = 0; h2 < 2; ++h2) {
            int grp = lg + 16 * h2;
            const float* ap = x + (size_t)(m0 + 4 * grp) * DMODEL + kt + lk;
            float4 va;
            va.x = ap[0];
            va.y = ap[DMODEL];
            va.z = ap[2 * DMODEL];
            va.w = ap[3 * DMODEL];
            *(float4*)&As[lk * 132 + 4 * grp] = va;
        }
        // W tile: rows n0+4*lg+j -> Bs[k][n]
        {
            const float* wp = W + (size_t)(n0 + 4 * lg) * DMODEL + kt + lk;
            float4 vb;
            vb.x = wp[0];
            vb.y = wp[DMODEL];
            vb.z = wp[2 * DMODEL];
            vb.w = wp[3 * DMODEL];
            *(float4*)&Bs[lk * 68 + 4 * lg] = vb;
        }
        __syncthreads();

#pragma unroll
        for (int k = 0; k < 16; ++k) {
            float4 a0 = *(const float4*)&As[k * 132 + 8 * ty];
            float4 a1 = *(const float4*)&As[k * 132 + 8 * ty + 4];
            float4 bb = *(const float4*)&Bs[k * 68 + 4 * tx];
            float aa[8] = {a0.x, a0.y, a0.z, a0.w, a1.x, a1.y, a1.z, a1.w};
            float bv[4] = {bb.x, bb.y, bb.z, bb.w};
#pragma unroll
            for (int i = 0; i < 8; ++i)
#pragma unroll
                for (int j = 0; j < 4; ++j)
                    acc[i][j] = fmaf(aa[i], bv[j], acc[i][j]);
        }
        __syncthreads();
    }

    // Epilogue: scatter to [b][h][s][dh], RoPE for q,k.
    const int ncol = n0 + 4 * tx;       // global model-dim column (4-aligned)
    const int h    = ncol >> 6;
    const int dh0  = ncol & 63;         // even; pairs (dh0,dh0+1),(dh0+2,dh0+3)
    float inv0 = 0.f, inv1 = 0.f;
    if (z < 2) {
        const float L2T = 13.287712379549449f;   // log2(10000)
        inv0 = exp2f(-(float)(dh0)     * (1.0f / 64.0f) * L2T);
        inv1 = exp2f(-(float)(dh0 + 2) * (1.0f / 64.0f) * L2T);
    }
#pragma unroll
    for (int i = 0; i < 8; ++i) {
        int m  = m0 + 8 * ty + i;
        int s  = m & (SLEN - 1);
        int bi = m >> 11;
        float* op = Out + (((size_t)(bi * NH + h) * SLEN + s) * HD + dh0);
        float4 o;
        if (z < 2) {
            float c0, s0, c1, s1;
            sincosf((float)s * inv0, &s0, &c0);
            sincosf((float)s * inv1, &s1, &c1);
            o.x = acc[i][0] * c0 - acc[i][1] * s0;
            o.y = acc[i][0] * s0 + acc[i][1] * c0;
            o.z = acc[i][2] * c1 - acc[i][3] * s1;
            o.w = acc[i][2] * s1 + acc[i][3] * c1;
        } else {
            o.x = acc[i][0]; o.y = acc[i][1]; o.z = acc[i][2]; o.w = acc[i][3];
        }
        *(float4*)op = o;
    }
}

// ---------------------------------------------------------------------------
// Flash attention: block = (q-tile 64 rows, one bh). 256 threads, 4x4 micro.
// Qs,Ks: [d=64][row=64] stride 68 (transposed, conflict-free)
// Vs:    [k=64][d=64] stride 64 ; Ps: [q=64][k=64] stride 64
// ---------------------------------------------------------------------------
#define ATTN_SMEM ((64 * 68 * 2 + 64 * 64 * 2) * 4)   // 67584 bytes

__global__ __launch_bounds__(256) void attn_kernel()
{
    extern __shared__ float sm[];
    float* Qs = sm;                  // 64*68
    float* Ks = sm + 64 * 68;        // 64*68
    float* Vs = Ks + 64 * 68;        // 64*64
    float* Ps = Vs + 64 * 64;        // 64*64

    const int bh = blockIdx.y;
    const int qt = (gridDim.x - 1) - blockIdx.x;   // heavy q-tiles first
    const int q0 = qt * 64;
    const float* __restrict__ qb = g_q + (size_t)bh * SLEN * HD;
    const float* __restrict__ kb = g_k + (size_t)bh * SLEN * HD;
    const float* __restrict__ vb = g_v + (size_t)bh * SLEN * HD;

    const int tid = threadIdx.x;
    const int tx = tid & 15, ty = tid >> 4;
    const int d  = tid & 63, g4 = tid >> 6;     // transposed-loader coords
    const int fr = tid >> 4, fc = tid & 15;     // V-loader coords

    // Load Q tile transposed: Qs[d][q]
#pragma unroll
    for (int it = 0; it < 4; ++it) {
        int grp = it * 4 + g4;
        const float* qp = qb + (size_t)(q0 + 4 * grp) * HD + d;
        float4 v;
        v.x = qp[0]; v.y = qp[HD]; v.z = qp[2 * HD]; v.w = qp[3 * HD];
        *(float4*)&Qs[d * 68 + 4 * grp] = v;
    }

    float m_i[4], l_i[4], acc[4][4];
#pragma unroll
    for (int i = 0; i < 4; ++i) {
        m_i[i] = -1e30f; l_i[i] = 0.f;
#pragma unroll
        for (int j = 0; j < 4; ++j) acc[i][j] = 0.f;
    }
    __syncthreads();

    for (int kt = 0; kt <= qt; ++kt) {
        const int k0 = kt * 64;
        // K tile transposed: Ks[d][k]
#pragma unroll
        for (int it = 0; it < 4; ++it) {
            int grp = it * 4 + g4;
            const float* kp = kb + (size_t)(k0 + 4 * grp) * HD + d;
            float4 v;
            v.x = kp[0]; v.y = kp[HD]; v.z = kp[2 * HD]; v.w = kp[3 * HD];
            *(float4*)&Ks[d * 68 + 4 * grp] = v;
        }
        // V tile natural: Vs[k][d]
#pragma unroll
        for (int it = 0; it < 4; ++it) {
            int r = fr + it * 16;
            *(float4*)&Vs[r * 64 + 4 * fc] =
                *(const float4*)&vb[(size_t)(k0 + r) * HD + 4 * fc];
        }
        __syncthreads();

        // Scores: sc[i][j] = Q[q0+4ty+i] . K[k0+4tx+j]
        float sc[4][4];
#pragma unroll
        for (int i = 0; i < 4; ++i)
#pragma unroll
            for (int j = 0; j < 4; ++j) sc[i][j] = 0.f;

#pragma unroll 8
        for (int dd = 0; dd < 64; ++dd) {
            float4 qv = *(const float4*)&Qs[dd * 68 + 4 * ty];
            float4 kv = *(const float4*)&Ks[dd * 68 + 4 * tx];
            float qa[4] = {qv.x, qv.y, qv.z, qv.w};
            float ka[4] = {kv.x, kv.y, kv.z, kv.w};
#pragma unroll
            for (int i = 0; i < 4; ++i)
#pragma unroll
                for (int j = 0; j < 4; ++j)
                    sc[i][j] = fmaf(qa[i], ka[j], sc[i][j]);
        }

        // scale + causal mask (diag tile only)
#pragma unroll
        for (int i = 0; i < 4; ++i)
#pragma unroll
            for (int j = 0; j < 4; ++j) {
                sc[i][j] *= 0.125f;   // 1/sqrt(64)
                if (kt == qt && (k0 + 4 * tx + j) > (q0 + 4 * ty + i))
                    sc[i][j] = -1e30f;
            }

        // online softmax (row stats shared by the 16-lane half-warp per ty)
#pragma unroll
        for (int i = 0; i < 4; ++i) {
            float mx = fmaxf(fmaxf(sc[i][0], sc[i][1]), fmaxf(sc[i][2], sc[i][3]));
#pragma unroll
            for (int off = 8; off > 0; off >>= 1)
                mx = fmaxf(mx, __shfl_xor_sync(0xffffffffu, mx, off, 16));
            float mnew = fmaxf(m_i[i], mx);
            float corr = __expf(m_i[i] - mnew);
            m_i[i] = mnew;
            float rs = 0.f;
#pragma unroll
            for (int j = 0; j < 4; ++j) {
                float p = __expf(sc[i][j] - mnew);
                sc[i][j] = p;
                rs += p;
            }
#pragma unroll
            for (int off = 8; off > 0; off >>= 1)
                rs += __shfl_xor_sync(0xffffffffu, rs, off, 16);
            l_i[i] = l_i[i] * corr + rs;
#pragma unroll
            for (int j = 0; j < 4; ++j) acc[i][j] *= corr;
        }

        // P -> smem for the PV GEMM
#pragma unroll
        for (int i = 0; i < 4; ++i)
            *(float4*)&Ps[(4 * ty + i) * 64 + 4 * tx] =
                make_float4(sc[i][0], sc[i][1], sc[i][2], sc[i][3]);
        __syncthreads();

        // O += P @ V
#pragma unroll 4
        for (int kk = 0; kk < 64; ++kk) {
            float4 vv = *(const float4*)&Vs[kk * 64 + 4 * tx];
#pragma unroll
            for (int i = 0; i < 4; ++i) {
                float p = Ps[(4 * ty + i) * 64 + kk];
                acc[i][0] = fmaf(p, vv.x, acc[i][0]);
                acc[i][1] = fmaf(p, vv.y, acc[i][1]);
                acc[i][2] = fmaf(p, vv.z, acc[i][2]);
                acc[i][3] = fmaf(p, vv.w, acc[i][3]);
            }
        }
        __syncthreads();
    }

    // Normalize and write back to [b][s][h*64+dh]
    const int b_ = bh >> 4, h = bh & 15;
#pragma unroll
    for (int i = 0; i < 4; ++i) {
        int s = q0 + 4 * ty + i;
        float inv = 1.0f / l_i[i];
        float4 o = make_float4(acc[i][0] * inv, acc[i][1] * inv,
                               acc[i][2] * inv, acc[i][3] * inv);
        *(float4*)&g_o[((size_t)(b_ * SLEN + s)) * DMODEL + h * HD + 4 * tx] = o;
    }
}

// ---------------------------------------------------------------------------
// Output projection: out[m][n] = sum_k g_o[m][k] * Wo[n][k]
// ---------------------------------------------------------------------------
__global__ __launch_bounds__(256) void out_proj_kernel(
    const float* __restrict__ Wo, float* __restrict__ out)
{
    __shared__ float As[16 * 132];
    __shared__ float Bs[16 * 68];

    const int m0 = blockIdx.x * 128;
    const int n0 = blockIdx.y * 64;
    const int tid = threadIdx.x;
    const int tx = tid & 15, ty = tid >> 4;
    const int lk = tid & 15, lg = tid >> 4;

    float acc[8][4];
#pragma unroll
    for (int i = 0; i < 8; ++i)
#pragma unroll
        for (int j = 0; j < 4; ++j) acc[i][j] = 0.f;

    for (int kt = 0; kt < DMODEL; kt += 16) {
#pragma unroll
        for (int h2 = 0; h2 < 2; ++h2) {
            int grp = lg + 16 * h2;
            const float* ap = g_o + (size_t)(m0 + 4 * grp) * DMODEL + kt + lk;
            float4 va;
            va.x = ap[0];
            va.y = ap[DMODEL];
            va.z = ap[2 * DMODEL];
            va.w = ap[3 * DMODEL];
            *(float4*)&As[lk * 132 + 4 * grp] = va;
        }
        {
            const float* wp = Wo + (size_t)(n0 + 4 * lg) * DMODEL + kt + lk;
            float4 vb;
            vb.x = wp[0];
            vb.y = wp[DMODEL];
            vb.z = wp[2 * DMODEL];
            vb.w = wp[3 * DMODEL];
            *(float4*)&Bs[lk * 68 + 4 * lg] = vb;
        }
        __syncthreads();

#pragma unroll
        for (int k = 0; k < 16; ++k) {
            float4 a0 = *(const float4*)&As[k * 132 + 8 * ty];
            float4 a1 = *(const float4*)&As[k * 132 + 8 * ty + 4];
            float4 bb = *(const float4*)&Bs[k * 68 + 4 * tx];
            float aa[8] = {a0.x, a0.y, a0.z, a0.w, a1.x, a1.y, a1.z, a1.w};
            float bv[4] = {bb.x, bb.y, bb.z, bb.w};
#pragma unroll
            for (int i = 0; i < 8; ++i)
#pragma unroll
                for (int j = 0; j < 4; ++j)
                    acc[i][j] = fmaf(aa[i], bv[j], acc[i][j]);
        }
        __syncthreads();
    }

#pragma unroll
    for (int i = 0; i < 8; ++i) {
        int m = m0 + 8 * ty + i;
        float4 o = make_float4(acc[i][0], acc[i][1], acc[i][2], acc[i][3]);
        *(float4*)&out[(size_t)m * DMODEL + n0 + 4 * tx] = o;
    }
}

// ---------------------------------------------------------------------------
extern "C" void kernel_launch(void* const* d_in, const int* in_sizes, int n_in,
                              void* d_out, int out_size)
{
    const float* x  = (const float*)d_in[0];
    const float* Wq = (const float*)d_in[1];
    const float* Wk = (const float*)d_in[2];
    const float* Wv = (const float*)d_in[3];
    const float* Wo = (const float*)d_in[4];
    float* out = (float*)d_out;

    cudaFuncSetAttribute(attn_kernel,
                         cudaFuncAttributeMaxDynamicSharedMemorySize, ATTN_SMEM);

    dim3 gp(MTOT / 128, DMODEL / 64, 3);
    qkv_proj_kernel<<<gp, 256>>>(x, Wq, Wk, Wv);

    dim3 ga(SLEN / 64, BNUM * NH);
    attn_kernel<<<ga, 256, ATTN_SMEM>>>();

    dim3 go(MTOT / 128, DMODEL / 64);
    out_proj_kernel<<<go, 256>>>(Wo, out);
}

// round 11
// speedup vs baseline: 1.1061x; 1.1061x over previous
#include <cuda_runtime.h>
#include <math.h>

#define BNUM   2
#define SLEN   2048
#define DMODEL 1024
#define NH     16
#define HD     64
#define MTOT   (BNUM * SLEN)   // 4096

// Scratch (static device globals -- allocation-free)
__device__ float g_q[BNUM * NH * SLEN * HD];   // [b][h][s][dh]
__device__ float g_k[BNUM * NH * SLEN * HD];
__device__ float g_v[BNUM * NH * SLEN * HD];
__device__ float g_o[MTOT * DMODEL];           // [b*s][d] attention output

// ---------------------------------------------------------------------------
// Projection GEMM core: C[m][n] = sum_k A[m][k] * W[n][k]
// 128x128 block tile, BK=16, 256 threads, 8x8 microtile, double-buffered smem.
// As/Bs: [k=16][row=128] stride 132 (register-transposed stores, conflict-free)
// LDS per k-step per thread: 4x LDS.128 = 64 B for 64 lane-FMA  (1.0 B/FMA)
// ---------------------------------------------------------------------------

// ---------------- QKV projection + fused RoPE --------------------------------
__global__ __launch_bounds__(256, 2) void qkv_proj_kernel(
    const float* __restrict__ x,
    const float* __restrict__ Wq,
    const float* __restrict__ Wk,
    const float* __restrict__ Wv)
{
    __shared__ float As[2][16 * 132];
    __shared__ float Bs[2][16 * 132];

    const int z = blockIdx.z;                    // 0=q 1=k 2=v
    const float* __restrict__ W = (z == 0) ? Wq : ((z == 1) ? Wk : Wv);
    float* __restrict__ Out     = (z == 0) ? g_q : ((z == 1) ? g_k : g_v);

    const int m0 = blockIdx.x * 128;
    const int n0 = blockIdx.y * 128;
    const int tid = threadIdx.x;
    const int tx = tid & 15, ty = tid >> 4;      // compute layout 16x16
    const int lk = tid & 15, lg = tid >> 4;      // loader layout

    // loop-invariant prefetch base pointers (advance by +16 each k-tile)
    const float* pa0 = x + (size_t)(m0 + 4 * lg) * DMODEL + lk;
    const float* pa1 = x + (size_t)(m0 + 4 * (lg + 16)) * DMODEL + lk;
    const float* pb0 = W + (size_t)(n0 + 4 * lg) * DMODEL + lk;
    const float* pb1 = W + (size_t)(n0 + 4 * (lg + 16)) * DMODEL + lk;

    float acc[8][8];
#pragma unroll
    for (int i = 0; i < 8; ++i)
#pragma unroll
        for (int j = 0; j < 8; ++j) acc[i][j] = 0.f;

    float4 ra[2], rb[2];

    // prologue: load k-tile 0
    ra[0].x = pa0[0]; ra[0].y = pa0[DMODEL]; ra[0].z = pa0[2 * DMODEL]; ra[0].w = pa0[3 * DMODEL];
    ra[1].x = pa1[0]; ra[1].y = pa1[DMODEL]; ra[1].z = pa1[2 * DMODEL]; ra[1].w = pa1[3 * DMODEL];
    rb[0].x = pb0[0]; rb[0].y = pb0[DMODEL]; rb[0].z = pb0[2 * DMODEL]; rb[0].w = pb0[3 * DMODEL];
    rb[1].x = pb1[0]; rb[1].y = pb1[DMODEL]; rb[1].z = pb1[2 * DMODEL]; rb[1].w = pb1[3 * DMODEL];
    *(float4*)&As[0][lk * 132 + 4 * lg]        = ra[0];
    *(float4*)&As[0][lk * 132 + 4 * (lg + 16)] = ra[1];
    *(float4*)&Bs[0][lk * 132 + 4 * lg]        = rb[0];
    *(float4*)&Bs[0][lk * 132 + 4 * (lg + 16)] = rb[1];
    __syncthreads();

    for (int kt = 0; kt < DMODEL; kt += 16) {
        const int cur = (kt >> 4) & 1;
        const bool more = (kt + 16) < DMODEL;
        if (more) {
            const float* qa0 = pa0 + kt + 16;
            const float* qa1 = pa1 + kt + 16;
            const float* qb0 = pb0 + kt + 16;
            const float* qb1 = pb1 + kt + 16;
            ra[0].x = qa0[0]; ra[0].y = qa0[DMODEL]; ra[0].z = qa0[2 * DMODEL]; ra[0].w = qa0[3 * DMODEL];
            ra[1].x = qa1[0]; ra[1].y = qa1[DMODEL]; ra[1].z = qa1[2 * DMODEL]; ra[1].w = qa1[3 * DMODEL];
            rb[0].x = qb0[0]; rb[0].y = qb0[DMODEL]; rb[0].z = qb0[2 * DMODEL]; rb[0].w = qb0[3 * DMODEL];
            rb[1].x = qb1[0]; rb[1].y = qb1[DMODEL]; rb[1].z = qb1[2 * DMODEL]; rb[1].w = qb1[3 * DMODEL];
        }
#pragma unroll
        for (int k = 0; k < 16; ++k) {
            float4 a0 = *(const float4*)&As[cur][k * 132 + 8 * ty];
            float4 a1 = *(const float4*)&As[cur][k * 132 + 8 * ty + 4];
            float4 b0 = *(const float4*)&Bs[cur][k * 132 + 4 * tx];
            float4 b1 = *(const float4*)&Bs[cur][k * 132 + 64 + 4 * tx];
            float aa[8] = {a0.x, a0.y, a0.z, a0.w, a1.x, a1.y, a1.z, a1.w};
            float bb[8] = {b0.x, b0.y, b0.z, b0.w, b1.x, b1.y, b1.z, b1.w};
#pragma unroll
            for (int i = 0; i < 8; ++i)
#pragma unroll
                for (int j = 0; j < 8; ++j)
                    acc[i][j] = fmaf(aa[i], bb[j], acc[i][j]);
        }
        if (more) {
            const int nxt = cur ^ 1;
            *(float4*)&As[nxt][lk * 132 + 4 * lg]        = ra[0];
            *(float4*)&As[nxt][lk * 132 + 4 * (lg + 16)] = ra[1];
            *(float4*)&Bs[nxt][lk * 132 + 4 * lg]        = rb[0];
            *(float4*)&Bs[nxt][lk * 132 + 4 * (lg + 16)] = rb[1];
            __syncthreads();
        }
    }

    // Epilogue: scatter to [b][h][s][dh]; RoPE for q,k.
    const float L2T = 13.287712379549449f;   // log2(10000)
#pragma unroll
    for (int g = 0; g < 2; ++g) {
        const int ncol = n0 + 64 * g + 4 * tx;   // 4-aligned model column
        const int h    = ncol >> 6;
        const int dh0  = ncol & 63;
        float inv0 = 0.f, inv1 = 0.f;
        if (z < 2) {
            inv0 = exp2f(-(float)(dh0)     * (1.0f / 64.0f) * L2T);
            inv1 = exp2f(-(float)(dh0 + 2) * (1.0f / 64.0f) * L2T);
        }
#pragma unroll
        for (int i = 0; i < 8; ++i) {
            int m  = m0 + 8 * ty + i;
            int s  = m & (SLEN - 1);
            int bi = m >> 11;
            float* op = Out + (((size_t)(bi * NH + h) * SLEN + s) * HD + dh0);
            float4 o;
            float v0 = acc[i][4 * g], v1 = acc[i][4 * g + 1];
            float v2 = acc[i][4 * g + 2], v3 = acc[i][4 * g + 3];
            if (z < 2) {
                float c0, s0, c1, s1;
                sincosf((float)s * inv0, &s0, &c0);
                sincosf((float)s * inv1, &s1, &c1);
                o.x = v0 * c0 - v1 * s0;
                o.y = v0 * s0 + v1 * c0;
                o.z = v2 * c1 - v3 * s1;
                o.w = v2 * s1 + v3 * c1;
            } else {
                o.x = v0; o.y = v1; o.z = v2; o.w = v3;
            }
            *(float4*)op = o;
        }
    }
}

// ---------------------------------------------------------------------------
// Flash attention: block = (128-row q-tile, one bh). 256 threads.
// QK: 128x128 scores, 8x8 micro (1.0 B/FMA). PV: 8q x 4d micro.
// Qs,Ks: [d=64][row=128] stride 132; Vs: [k=128][d=64] stride 68;
// Ps: [q=128][k] stride 132.  1/sqrt(d) folded into Qs store.
// Total dynamic smem: (64*132*2 + 128*68 + 128*132)*4 = 169,984 B < 227 KB cap.
// ---------------------------------------------------------------------------
#define ATTN_SMEM ((64 * 132 * 2 + 128 * 68 + 128 * 132) * 4)

__global__ __launch_bounds__(256, 1) void attn_kernel()
{
    extern __shared__ float sm[];
    float* Qs = sm;                    // 64*132
    float* Ks = Qs + 64 * 132;         // 64*132
    float* Vs = Ks + 64 * 132;         // 128*68
    float* Ps = Vs + 128 * 68;         // 128*132

    const int bh = blockIdx.y;
    const int qt = (gridDim.x - 1) - blockIdx.x;   // heavy q-tiles first
    const int q0 = qt * 128;
    const float* __restrict__ qb = g_q + (size_t)bh * SLEN * HD;
    const float* __restrict__ kb = g_k + (size_t)bh * SLEN * HD;
    const float* __restrict__ vb = g_v + (size_t)bh * SLEN * HD;

    const int tid = threadIdx.x;
    const int tx = tid & 15, ty = tid >> 4;
    const int d  = tid & 63, g4 = tid >> 6;     // transposed-loader coords
    const int fr = tid >> 4, fc = tid & 15;     // V-loader coords

    // Load Q tile transposed + pre-scaled: Qs[d][q] = Q * 0.125
#pragma unroll
    for (int it = 0; it < 8; ++it) {
        int grp = it * 4 + g4;
        const float* qp = qb + (size_t)(q0 + 4 * grp) * HD + d;
        float4 v;
        v.x = qp[0] * 0.125f;       v.y = qp[HD] * 0.125f;
        v.z = qp[2 * HD] * 0.125f;  v.w = qp[3 * HD] * 0.125f;
        *(float4*)&Qs[d * 132 + 4 * grp] = v;
    }

    float m_i[8], l_i[8], acc[8][4];
#pragma unroll
    for (int i = 0; i < 8; ++i) {
        m_i[i] = -1e30f; l_i[i] = 0.f;
#pragma unroll
        for (int j = 0; j < 4; ++j) acc[i][j] = 0.f;
    }
    __syncthreads();

    for (int kt = 0; kt <= qt; ++kt) {
        const int k0 = kt * 128;
        // K tile transposed: Ks[d][k]
#pragma unroll
        for (int it = 0; it < 8; ++it) {
            int grp = it * 4 + g4;
            const float* kp = kb + (size_t)(k0 + 4 * grp) * HD + d;
            float4 v;
            v.x = kp[0]; v.y = kp[HD]; v.z = kp[2 * HD]; v.w = kp[3 * HD];
            *(float4*)&Ks[d * 132 + 4 * grp] = v;
        }
        // V tile natural: Vs[k][d]
#pragma unroll
        for (int it = 0; it < 8; ++it) {
            int r = fr + 16 * it;
            *(float4*)&Vs[r * 68 + 4 * fc] =
                *(const float4*)&vb[(size_t)(k0 + r) * HD + 4 * fc];
        }
        __syncthreads();

        // ---- scores: sc[i][j] = Qrow(8ty+i) . Kcol(8tx+j), pre-scaled ----
        float sc[8][8];
#pragma unroll
        for (int i = 0; i < 8; ++i)
#pragma unroll
            for (int j = 0; j < 8; ++j) sc[i][j] = 0.f;

#pragma unroll 4
        for (int dd = 0; dd < 64; ++dd) {
            float4 q0f = *(const float4*)&Qs[dd * 132 + 8 * ty];
            float4 q1f = *(const float4*)&Qs[dd * 132 + 8 * ty + 4];
            float4 k0f = *(const float4*)&Ks[dd * 132 + 8 * tx];
            float4 k1f = *(const float4*)&Ks[dd * 132 + 8 * tx + 4];
            float qa[8] = {q0f.x, q0f.y, q0f.z, q0f.w, q1f.x, q1f.y, q1f.z, q1f.w};
            float ka[8] = {k0f.x, k0f.y, k0f.z, k0f.w, k1f.x, k1f.y, k1f.z, k1f.w};
#pragma unroll
            for (int i = 0; i < 8; ++i)
#pragma unroll
                for (int j = 0; j < 8; ++j)
                    sc[i][j] = fmaf(qa[i], ka[j], sc[i][j]);
        }

        // causal mask (diagonal tile only; k0 == q0 there)
        if (kt == qt) {
#pragma unroll
            for (int i = 0; i < 8; ++i)
#pragma unroll
                for (int j = 0; j < 8; ++j)
                    if ((8 * tx + j) > (8 * ty + i)) sc[i][j] = -1e30f;
        }

        // ---- online softmax (row stats shared by the 16-lane half-warp) ----
#pragma unroll
        for (int i = 0; i < 8; ++i) {
            float mx = sc[i][0];
#pragma unroll
            for (int j = 1; j < 8; ++j) mx = fmaxf(mx, sc[i][j]);
#pragma unroll
            for (int off = 8; off > 0; off >>= 1)
                mx = fmaxf(mx, __shfl_xor_sync(0xffffffffu, mx, off, 16));
            float mnew = fmaxf(m_i[i], mx);
            float corr = __expf(m_i[i] - mnew);
            m_i[i] = mnew;
            float rs = 0.f;
#pragma unroll
            for (int j = 0; j < 8; ++j) {
                float p = __expf(sc[i][j] - mnew);
                sc[i][j] = p;
                rs += p;
            }
#pragma unroll
            for (int off = 8; off > 0; off >>= 1)
                rs += __shfl_xor_sync(0xffffffffu, rs, off, 16);
            l_i[i] = l_i[i] * corr + rs;
#pragma unroll
            for (int j = 0; j < 4; ++j) acc[i][j] *= corr;
            // P row -> smem
            *(float4*)&Ps[(8 * ty + i) * 132 + 8 * tx] =
                make_float4(sc[i][0], sc[i][1], sc[i][2], sc[i][3]);
            *(float4*)&Ps[(8 * ty + i) * 132 + 8 * tx + 4] =
                make_float4(sc[i][4], sc[i][5], sc[i][6], sc[i][7]);
        }
        __syncthreads();

        // ---- O += P @ V  (rows 8ty+i, d-cols 4tx..4tx+3) ----
#pragma unroll 2
        for (int kk4 = 0; kk4 < 32; ++kk4) {
            float4 vv[4];
#pragma unroll
            for (int c = 0; c < 4; ++c)
                vv[c] = *(const float4*)&Vs[(4 * kk4 + c) * 68 + 4 * tx];
#pragma unroll
            for (int i = 0; i < 8; ++i) {
                float4 p = *(const float4*)&Ps[(8 * ty + i) * 132 + 4 * kk4];
                acc[i][0] = fmaf(p.x, vv[0].x, acc[i][0]);
                acc[i][1] = fmaf(p.x, vv[0].y, acc[i][1]);
                acc[i][2] = fmaf(p.x, vv[0].z, acc[i][2]);
                acc[i][3] = fmaf(p.x, vv[0].w, acc[i][3]);
                acc[i][0] = fmaf(p.y, vv[1].x, acc[i][0]);
                acc[i][1] = fmaf(p.y, vv[1].y, acc[i][1]);
                acc[i][2] = fmaf(p.y, vv[1].z, acc[i][2]);
                acc[i][3] = fmaf(p.y, vv[1].w, acc[i][3]);
                acc[i][0] = fmaf(p.z, vv[2].x, acc[i][0]);
                acc[i][1] = fmaf(p.z, vv[2].y, acc[i][1]);
                acc[i][2] = fmaf(p.z, vv[2].z, acc[i][2]);
                acc[i][3] = fmaf(p.z, vv[2].w, acc[i][3]);
                acc[i][0] = fmaf(p.w, vv[3].x, acc[i][0]);
                acc[i][1] = fmaf(p.w, vv[3].y, acc[i][1]);
                acc[i][2] = fmaf(p.w, vv[3].z, acc[i][2]);
                acc[i][3] = fmaf(p.w, vv[3].w, acc[i][3]);
            }
        }
        __syncthreads();
    }

    // Normalize and write back to [b][s][h*64+dh]
    const int b_ = bh >> 4, h = bh & 15;
#pragma unroll
    for (int i = 0; i < 8; ++i) {
        int s = q0 + 8 * ty + i;
        float inv = 1.0f / l_i[i];
        float4 o = make_float4(acc[i][0] * inv, acc[i][1] * inv,
                               acc[i][2] * inv, acc[i][3] * inv);
        *(float4*)&g_o[((size_t)(b_ * SLEN + s)) * DMODEL + h * HD + 4 * tx] = o;
    }
}

// ---------------------------------------------------------------------------
// Output projection: out[m][n] = sum_k g_o[m][k] * Wo[n][k]
// Same 128x128 / 8x8 double-buffered GEMM, plain epilogue.
// ---------------------------------------------------------------------------
__global__ __launch_bounds__(256, 2) void out_proj_kernel(
    const float* __restrict__ Wo, float* __restrict__ out)
{
    __shared__ float As[2][16 * 132];
    __shared__ float Bs[2][16 * 132];

    const int m0 = blockIdx.x * 128;
    const int n0 = blockIdx.y * 128;
    const int tid = threadIdx.x;
    const int tx = tid & 15, ty = tid >> 4;
    const int lk = tid & 15, lg = tid >> 4;

    const float* pa0 = g_o + (size_t)(m0 + 4 * lg) * DMODEL + lk;
    const float* pa1 = g_o + (size_t)(m0 + 4 * (lg + 16)) * DMODEL + lk;
    const float* pb0 = Wo + (size_t)(n0 + 4 * lg) * DMODEL + lk;
    const float* pb1 = Wo + (size_t)(n0 + 4 * (lg + 16)) * DMODEL + lk;

    float acc[8][8];
#pragma unroll
    for (int i = 0; i < 8; ++i)
#pragma unroll
        for (int j = 0; j < 8; ++j) acc[i][j] = 0.f;

    float4 ra[2], rb[2];
    ra[0].x = pa0[0]; ra[0].y = pa0[DMODEL]; ra[0].z = pa0[2 * DMODEL]; ra[0].w = pa0[3 * DMODEL];
    ra[1].x = pa1[0]; ra[1].y = pa1[DMODEL]; ra[1].z = pa1[2 * DMODEL]; ra[1].w = pa1[3 * DMODEL];
    rb[0].x = pb0[0]; rb[0].y = pb0[DMODEL]; rb[0].z = pb0[2 * DMODEL]; rb[0].w = pb0[3 * DMODEL];
    rb[1].x = pb1[0]; rb[1].y = pb1[DMODEL]; rb[1].z = pb1[2 * DMODEL]; rb[1].w = pb1[3 * DMODEL];
    *(float4*)&As[0][lk * 132 + 4 * lg]        = ra[0];
    *(float4*)&As[0][lk * 132 + 4 * (lg + 16)] = ra[1];
    *(float4*)&Bs[0][lk * 132 + 4 * lg]        = rb[0];
    *(float4*)&Bs[0][lk * 132 + 4 * (lg + 16)] = rb[1];
    __syncthreads();

    for (int kt = 0; kt < DMODEL; kt += 16) {
        const int cur = (kt >> 4) & 1;
        const bool more = (kt + 16) < DMODEL;
        if (more) {
            const float* qa0 = pa0 + kt + 16;
            const float* qa1 = pa1 + kt + 16;
            const float* qb0 = pb0 + kt + 16;
            const float* qb1 = pb1 + kt + 16;
            ra[0].x = qa0[0]; ra[0].y = qa0[DMODEL]; ra[0].z = qa0[2 * DMODEL]; ra[0].w = qa0[3 * DMODEL];
            ra[1].x = qa1[0]; ra[1].y = qa1[DMODEL]; ra[1].z = qa1[2 * DMODEL]; ra[1].w = qa1[3 * DMODEL];
            rb[0].x = qb0[0]; rb[0].y = qb0[DMODEL]; rb[0].z = qb0[2 * DMODEL]; rb[0].w = qb0[3 * DMODEL];
            rb[1].x = qb1[0]; rb[1].y = qb1[DMODEL]; rb[1].z = qb1[2 * DMODEL]; rb[1].w = qb1[3 * DMODEL];
        }
#pragma unroll
        for (int k = 0; k < 16; ++k) {
            float4 a0 = *(const float4*)&As[cur][k * 132 + 8 * ty];
            float4 a1 = *(const float4*)&As[cur][k * 132 + 8 * ty + 4];
            float4 b0 = *(const float4*)&Bs[cur][k * 132 + 4 * tx];
            float4 b1 = *(const float4*)&Bs[cur][k * 132 + 64 + 4 * tx];
            float aa[8] = {a0.x, a0.y, a0.z, a0.w, a1.x, a1.y, a1.z, a1.w};
            float bb[8] = {b0.x, b0.y, b0.z, b0.w, b1.x, b1.y, b1.z, b1.w};
#pragma unroll
            for (int i = 0; i < 8; ++i)
#pragma unroll
                for (int j = 0; j < 8; ++j)
                    acc[i][j] = fmaf(aa[i], bb[j], acc[i][j]);
        }
        if (more) {
            const int nxt = cur ^ 1;
            *(float4*)&As[nxt][lk * 132 + 4 * lg]        = ra[0];
            *(float4*)&As[nxt][lk * 132 + 4 * (lg + 16)] = ra[1];
            *(float4*)&Bs[nxt][lk * 132 + 4 * lg]        = rb[0];
            *(float4*)&Bs[nxt][lk * 132 + 4 * (lg + 16)] = rb[1];
            __syncthreads();
        }
    }

#pragma unroll
    for (int g = 0; g < 2; ++g)
#pragma unroll
        for (int i = 0; i < 8; ++i) {
            int m = m0 + 8 * ty + i;
            float4 o = make_float4(acc[i][4 * g], acc[i][4 * g + 1],
                                   acc[i][4 * g + 2], acc[i][4 * g + 3]);
            *(float4*)&out[(size_t)m * DMODEL + n0 + 64 * g + 4 * tx] = o;
        }
}

// ---------------------------------------------------------------------------
extern "C" void kernel_launch(void* const* d_in, const int* in_sizes, int n_in,
                              void* d_out, int out_size)
{
    const float* x  = (const float*)d_in[0];
    const float* Wq = (const float*)d_in[1];
    const float* Wk = (const float*)d_in[2];
    const float* Wv = (const float*)d_in[3];
    const float* Wo = (const float*)d_in[4];
    float* out = (float*)d_out;

    cudaFuncSetAttribute(attn_kernel,
                         cudaFuncAttributeMaxDynamicSharedMemorySize, ATTN_SMEM);

    dim3 gp(MTOT / 128, DMODEL / 128, 3);
    qkv_proj_kernel<<<gp, 256>>>(x, Wq, Wk, Wv);

    dim3 ga(SLEN / 128, BNUM * NH);
    attn_kernel<<<ga, 256, ATTN_SMEM>>>();

    dim3 go(MTOT / 128, DMODEL / 128);
    out_proj_kernel<<<go, 256>>>(Wo, out);
}

// round 15
// speedup vs baseline: 1.2372x; 1.1185x over previous
#include <cuda_runtime.h>
#include <math.h>

#define BNUM   2
#define SLEN   2048
#define DMODEL 1024
#define NH     16
#define HD     64
#define MTOT   (BNUM * SLEN)   // 4096

typedef unsigned long long u64;

// packed fp32x2 helpers (sm_103a FFMA2 path — ptxas only emits via PTX f32x2)
__device__ __forceinline__ u64 pack2(float lo, float hi) {
    u64 r; asm("mov.b64 %0, {%1, %2};" : "=l"(r) : "f"(lo), "f"(hi)); return r;
}
__device__ __forceinline__ u64 dup2(float v) {
    u64 r; asm("mov.b64 %0, {%1, %1};" : "=l"(r) : "f"(v)); return r;
}
__device__ __forceinline__ void ffma2(u64& d, u64 a, u64 b) {
    asm("fma.rn.f32x2 %0, %1, %2, %0;" : "+l"(d) : "l"(a), "l"(b));
}
__device__ __forceinline__ float2 unpack2(u64 v) {
    float2 f; asm("mov.b64 {%0, %1}, %2;" : "=f"(f.x), "=f"(f.y) : "l"(v)); return f;
}

// Scratch (static device globals -- allocation-free)
__device__ float g_q[BNUM * NH * SLEN * HD];   // [b][h][s][dh]
__device__ float g_k[BNUM * NH * SLEN * HD];
__device__ float g_v[BNUM * NH * SLEN * HD];
__device__ float g_o[MTOT * DMODEL];           // [b*s][d] attention output

// ---------------------------------------------------------------------------
// Projection GEMM core: C[m][n] = sum_k A[m][k] * W[n][k]
// 128x128 tile, BK=16, 256 threads, 8x8 microtile (as 8x4 f32x2 pairs),
// double-buffered smem. As/Bs: [k=16][row=128] stride 132, conflict-free.
// ---------------------------------------------------------------------------

// ---------------- QKV projection + fused RoPE --------------------------------
__global__ __launch_bounds__(256, 2) void qkv_proj_kernel(
    const float* __restrict__ x,
    const float* __restrict__ Wq,
    const float* __restrict__ Wk,
    const float* __restrict__ Wv)
{
    __shared__ float As[2][16 * 132];
    __shared__ float Bs[2][16 * 132];

    const int z = blockIdx.z;                    // 0=q 1=k 2=v
    const float* __restrict__ W = (z == 0) ? Wq : ((z == 1) ? Wk : Wv);
    float* __restrict__ Out     = (z == 0) ? g_q : ((z == 1) ? g_k : g_v);

    const int m0 = blockIdx.x * 128;
    const int n0 = blockIdx.y * 128;
    const int tid = threadIdx.x;
    const int tx = tid & 15, ty = tid >> 4;      // compute layout 16x16
    const int lk = tid & 15, lg = tid >> 4;      // loader layout

    const float* pa0 = x + (size_t)(m0 + 4 * lg) * DMODEL + lk;
    const float* pa1 = x + (size_t)(m0 + 4 * (lg + 16)) * DMODEL + lk;
    const float* pb0 = W + (size_t)(n0 + 4 * lg) * DMODEL + lk;
    const float* pb1 = W + (size_t)(n0 + 4 * (lg + 16)) * DMODEL + lk;

    u64 accp[8][4];                              // j-pairs: cols (2jp, 2jp+1)
#pragma unroll
    for (int i = 0; i < 8; ++i)
#pragma unroll
        for (int jp = 0; jp < 4; ++jp) accp[i][jp] = 0ull;

    float4 ra[2], rb[2];

    // prologue: load k-tile 0
    ra[0].x = pa0[0]; ra[0].y = pa0[DMODEL]; ra[0].z = pa0[2 * DMODEL]; ra[0].w = pa0[3 * DMODEL];
    ra[1].x = pa1[0]; ra[1].y = pa1[DMODEL]; ra[1].z = pa1[2 * DMODEL]; ra[1].w = pa1[3 * DMODEL];
    rb[0].x = pb0[0]; rb[0].y = pb0[DMODEL]; rb[0].z = pb0[2 * DMODEL]; rb[0].w = pb0[3 * DMODEL];
    rb[1].x = pb1[0]; rb[1].y = pb1[DMODEL]; rb[1].z = pb1[2 * DMODEL]; rb[1].w = pb1[3 * DMODEL];
    *(float4*)&As[0][lk * 132 + 4 * lg]        = ra[0];
    *(float4*)&As[0][lk * 132 + 4 * (lg + 16)] = ra[1];
    *(float4*)&Bs[0][lk * 132 + 4 * lg]        = rb[0];
    *(float4*)&Bs[0][lk * 132 + 4 * (lg + 16)] = rb[1];
    __syncthreads();

    for (int kt = 0; kt < DMODEL; kt += 16) {
        const int cur = (kt >> 4) & 1;
        const bool more = (kt + 16) < DMODEL;
        if (more) {
            const float* qa0 = pa0 + kt + 16;
            const float* qa1 = pa1 + kt + 16;
            const float* qb0 = pb0 + kt + 16;
            const float* qb1 = pb1 + kt + 16;
            ra[0].x = qa0[0]; ra[0].y = qa0[DMODEL]; ra[0].z = qa0[2 * DMODEL]; ra[0].w = qa0[3 * DMODEL];
            ra[1].x = qa1[0]; ra[1].y = qa1[DMODEL]; ra[1].z = qa1[2 * DMODEL]; ra[1].w = qa1[3 * DMODEL];
            rb[0].x = qb0[0]; rb[0].y = qb0[DMODEL]; rb[0].z = qb0[2 * DMODEL]; rb[0].w = qb0[3 * DMODEL];
            rb[1].x = qb1[0]; rb[1].y = qb1[DMODEL]; rb[1].z = qb1[2 * DMODEL]; rb[1].w = qb1[3 * DMODEL];
        }
#pragma unroll
        for (int k = 0; k < 16; ++k) {
            float4 a0 = *(const float4*)&As[cur][k * 132 + 8 * ty];
            float4 a1 = *(const float4*)&As[cur][k * 132 + 8 * ty + 4];
            float4 b0 = *(const float4*)&Bs[cur][k * 132 + 4 * tx];
            float4 b1 = *(const float4*)&Bs[cur][k * 132 + 64 + 4 * tx];
            u64 bp[4];
            bp[0] = pack2(b0.x, b0.y); bp[1] = pack2(b0.z, b0.w);
            bp[2] = pack2(b1.x, b1.y); bp[3] = pack2(b1.z, b1.w);
            float aa[8] = {a0.x, a0.y, a0.z, a0.w, a1.x, a1.y, a1.z, a1.w};
#pragma unroll
            for (int i = 0; i < 8; ++i) {
                u64 ad = dup2(aa[i]);
                ffma2(accp[i][0], ad, bp[0]);
                ffma2(accp[i][1], ad, bp[1]);
                ffma2(accp[i][2], ad, bp[2]);
                ffma2(accp[i][3], ad, bp[3]);
            }
        }
        if (more) {
            const int nxt = cur ^ 1;
            *(float4*)&As[nxt][lk * 132 + 4 * lg]        = ra[0];
            *(float4*)&As[nxt][lk * 132 + 4 * (lg + 16)] = ra[1];
            *(float4*)&Bs[nxt][lk * 132 + 4 * lg]        = rb[0];
            *(float4*)&Bs[nxt][lk * 132 + 4 * (lg + 16)] = rb[1];
            __syncthreads();
        }
    }

    // Epilogue: scatter to [b][h][s][dh]; RoPE for q,k.
    const float L2T = 13.287712379549449f;   // log2(10000)
#pragma unroll
    for (int g = 0; g < 2; ++g) {
        const int ncol = n0 + 64 * g + 4 * tx;   // 4-aligned model column
        const int h    = ncol >> 6;
        const int dh0  = ncol & 63;
        float inv0 = 0.f, inv1 = 0.f;
        if (z < 2) {
            inv0 = exp2f(-(float)(dh0)     * (1.0f / 64.0f) * L2T);
            inv1 = exp2f(-(float)(dh0 + 2) * (1.0f / 64.0f) * L2T);
        }
#pragma unroll
        for (int i = 0; i < 8; ++i) {
            int m  = m0 + 8 * ty + i;
            int s  = m & (SLEN - 1);
            int bi = m >> 11;
            float* op = Out + (((size_t)(bi * NH + h) * SLEN + s) * HD + dh0);
            float2 f0 = unpack2(accp[i][2 * g]);
            float2 f1 = unpack2(accp[i][2 * g + 1]);
            float4 o;
            if (z < 2) {
                float c0, s0, c1, s1;
                sincosf((float)s * inv0, &s0, &c0);
                sincosf((float)s * inv1, &s1, &c1);
                o.x = f0.x * c0 - f0.y * s0;
                o.y = f0.x * s0 + f0.y * c0;
                o.z = f1.x * c1 - f1.y * s1;
                o.w = f1.x * s1 + f1.y * c1;
            } else {
                o.x = f0.x; o.y = f0.y; o.z = f1.x; o.w = f1.y;
            }
            *(float4*)op = o;
        }
    }
}

// ---------------------------------------------------------------------------
// Flash attention: block = (128-row q-tile, one bh). 256 threads.
// QK: 128x128 scores, 8x8 micro via f32x2 pairs. PV: 8q x 4d via f32x2.
// Qs,Ks: [d=64][row=128] stride 132; Vs: [k=128][d=64] stride 68;
// Ps: [q=128][k] stride 132.  1/sqrt(d) folded into Qs store.
// ---------------------------------------------------------------------------
#define ATTN_SMEM ((64 * 132 * 2 + 128 * 68 + 128 * 132) * 4)   // 169984 B

__global__ __launch_bounds__(256, 1) void attn_kernel()
{
    extern __shared__ float sm[];
    float* Qs = sm;                    // 64*132
    float* Ks = Qs + 64 * 132;         // 64*132
    float* Vs = Ks + 64 * 132;         // 128*68
    float* Ps = Vs + 128 * 68;         // 128*132

    const int bh = blockIdx.y;
    const int qt = (gridDim.x - 1) - blockIdx.x;   // heavy q-tiles first
    const int q0 = qt * 128;
    const float* __restrict__ qb = g_q + (size_t)bh * SLEN * HD;
    const float* __restrict__ kb = g_k + (size_t)bh * SLEN * HD;
    const float* __restrict__ vb = g_v + (size_t)bh * SLEN * HD;

    const int tid = threadIdx.x;
    const int tx = tid & 15, ty = tid >> 4;
    const int d  = tid & 63, g4 = tid >> 6;     // transposed-loader coords
    const int fr = tid >> 4, fc = tid & 15;     // V-loader coords

    // Load Q tile transposed + pre-scaled: Qs[d][q] = Q * 0.125
#pragma unroll
    for (int it = 0; it < 8; ++it) {
        int grp = it * 4 + g4;
        const float* qp = qb + (size_t)(q0 + 4 * grp) * HD + d;
        float4 v;
        v.x = qp[0] * 0.125f;       v.y = qp[HD] * 0.125f;
        v.z = qp[2 * HD] * 0.125f;  v.w = qp[3 * HD] * 0.125f;
        *(float4*)&Qs[d * 132 + 4 * grp] = v;
    }

    float m_i[8], l_i[8];
    u64 accp[8][2];                     // d-col pairs (4tx+0,1) and (4tx+2,3)
#pragma unroll
    for (int i = 0; i < 8; ++i) {
        m_i[i] = -1e30f; l_i[i] = 0.f;
        accp[i][0] = 0ull; accp[i][1] = 0ull;
    }
    __syncthreads();

    for (int kt = 0; kt <= qt; ++kt) {
        const int k0 = kt * 128;
        // K tile transposed: Ks[d][k]
#pragma unroll
        for (int it = 0; it < 8; ++it) {
            int grp = it * 4 + g4;
            const float* kp = kb + (size_t)(k0 + 4 * grp) * HD + d;
            float4 v;
            v.x = kp[0]; v.y = kp[HD]; v.z = kp[2 * HD]; v.w = kp[3 * HD];
            *(float4*)&Ks[d * 132 + 4 * grp] = v;
        }
        // V tile natural: Vs[k][d]
#pragma unroll
        for (int it = 0; it < 8; ++it) {
            int r = fr + 16 * it;
            *(float4*)&Vs[r * 68 + 4 * fc] =
                *(const float4*)&vb[(size_t)(k0 + r) * HD + 4 * fc];
        }
        __syncthreads();

        // ---- scores: pairs scp[i][jp] = cols (8tx+2jp, 8tx+2jp+1) ----
        u64 scp[8][4];
#pragma unroll
        for (int i = 0; i < 8; ++i)
#pragma unroll
            for (int jp = 0; jp < 4; ++jp) scp[i][jp] = 0ull;

#pragma unroll 4
        for (int dd = 0; dd < 64; ++dd) {
            float4 q0f = *(const float4*)&Qs[dd * 132 + 8 * ty];
            float4 q1f = *(const float4*)&Qs[dd * 132 + 8 * ty + 4];
            float4 k0f = *(const float4*)&Ks[dd * 132 + 8 * tx];
            float4 k1f = *(const float4*)&Ks[dd * 132 + 8 * tx + 4];
            u64 kp2[4];
            kp2[0] = pack2(k0f.x, k0f.y); kp2[1] = pack2(k0f.z, k0f.w);
            kp2[2] = pack2(k1f.x, k1f.y); kp2[3] = pack2(k1f.z, k1f.w);
            float qa[8] = {q0f.x, q0f.y, q0f.z, q0f.w, q1f.x, q1f.y, q1f.z, q1f.w};
#pragma unroll
            for (int i = 0; i < 8; ++i) {
                u64 qd = dup2(qa[i]);
                ffma2(scp[i][0], qd, kp2[0]);
                ffma2(scp[i][1], qd, kp2[1]);
                ffma2(scp[i][2], qd, kp2[2]);
                ffma2(scp[i][3], qd, kp2[3]);
            }
        }

        // unpack to scalars for mask + softmax
        float sc[8][8];
#pragma unroll
        for (int i = 0; i < 8; ++i)
#pragma unroll
            for (int jp = 0; jp < 4; ++jp) {
                float2 f = unpack2(scp[i][jp]);
                sc[i][2 * jp] = f.x; sc[i][2 * jp + 1] = f.y;
            }

        // causal mask (diagonal tile only; k0 == q0 there)
        if (kt == qt) {
#pragma unroll
            for (int i = 0; i < 8; ++i)
#pragma unroll
                for (int j = 0; j < 8; ++j)
                    if ((8 * tx + j) > (8 * ty + i)) sc[i][j] = -1e30f;
        }

        // ---- online softmax (row stats shared by the 16-lane half-warp) ----
#pragma unroll
        for (int i = 0; i < 8; ++i) {
            float mx = sc[i][0];
#pragma unroll
            for (int j = 1; j < 8; ++j) mx = fmaxf(mx, sc[i][j]);
#pragma unroll
            for (int off = 8; off > 0; off >>= 1)
                mx = fmaxf(mx, __shfl_xor_sync(0xffffffffu, mx, off, 16));
            float mnew = fmaxf(m_i[i], mx);
            float corr = __expf(m_i[i] - mnew);
            m_i[i] = mnew;
            float rs = 0.f;
#pragma unroll
            for (int j = 0; j < 8; ++j) {
                float p = __expf(sc[i][j] - mnew);
                sc[i][j] = p;
                rs += p;
            }
#pragma unroll
            for (int off = 8; off > 0; off >>= 1)
                rs += __shfl_xor_sync(0xffffffffu, rs, off, 16);
            l_i[i] = l_i[i] * corr + rs;
            u64 cd = dup2(corr);
            // acc *= corr  (packed: acc = acc*corr + 0)
            {
                u64 t0 = accp[i][0], t1 = accp[i][1];
                accp[i][0] = 0ull; accp[i][1] = 0ull;
                ffma2(accp[i][0], cd, t0);
                ffma2(accp[i][1], cd, t1);
            }
            // P row -> smem
            *(float4*)&Ps[(8 * ty + i) * 132 + 8 * tx] =
                make_float4(sc[i][0], sc[i][1], sc[i][2], sc[i][3]);
            *(float4*)&Ps[(8 * ty + i) * 132 + 8 * tx + 4] =
                make_float4(sc[i][4], sc[i][5], sc[i][6], sc[i][7]);
        }
        __syncthreads();

        // ---- O += P @ V  (rows 8ty+i, d-col pairs at 4tx) ----
#pragma unroll 2
        for (int kk4 = 0; kk4 < 32; ++kk4) {
            u64 vp[4][2];
#pragma unroll
            for (int c = 0; c < 4; ++c) {
                float4 vv = *(const float4*)&Vs[(4 * kk4 + c) * 68 + 4 * tx];
                vp[c][0] = pack2(vv.x, vv.y);
                vp[c][1] = pack2(vv.z, vv.w);
            }
#pragma unroll
            for (int i = 0; i < 8; ++i) {
                float4 p = *(const float4*)&Ps[(8 * ty + i) * 132 + 4 * kk4];
                u64 p0 = dup2(p.x), p1 = dup2(p.y), p2 = dup2(p.z), p3 = dup2(p.w);
                ffma2(accp[i][0], p0, vp[0][0]); ffma2(accp[i][1], p0, vp[0][1]);
                ffma2(accp[i][0], p1, vp[1][0]); ffma2(accp[i][1], p1, vp[1][1]);
                ffma2(accp[i][0], p2, vp[2][0]); ffma2(accp[i][1], p2, vp[2][1]);
                ffma2(accp[i][0], p3, vp[3][0]); ffma2(accp[i][1], p3, vp[3][1]);
            }
        }
        __syncthreads();
    }

    // Normalize and write back to [b][s][h*64+dh]
    const int b_ = bh >> 4, h = bh & 15;
#pragma unroll
    for (int i = 0; i < 8; ++i) {
        int s = q0 + 8 * ty + i;
        float inv = 1.0f / l_i[i];
        float2 f0 = unpack2(accp[i][0]);
        float2 f1 = unpack2(accp[i][1]);
        float4 o = make_float4(f0.x * inv, f0.y * inv, f1.x * inv, f1.y * inv);
        *(float4*)&g_o[((size_t)(b_ * SLEN + s)) * DMODEL + h * HD + 4 * tx] = o;
    }
}

// ---------------------------------------------------------------------------
// Output projection: out[m][n] = sum_k g_o[m][k] * Wo[n][k]
// Same 128x128 / 8x8 double-buffered GEMM (f32x2), plain epilogue.
// ---------------------------------------------------------------------------
__global__ __launch_bounds__(256, 2) void out_proj_kernel(
    const float* __restrict__ Wo, float* __restrict__ out)
{
    __shared__ float As[2][16 * 132];
    __shared__ float Bs[2][16 * 132];

    const int m0 = blockIdx.x * 128;
    const int n0 = blockIdx.y * 128;
    const int tid = threadIdx.x;
    const int tx = tid & 15, ty = tid >> 4;
    const int lk = tid & 15, lg = tid >> 4;

    const float* pa0 = g_o + (size_t)(m0 + 4 * lg) * DMODEL + lk;
    const float* pa1 = g_o + (size_t)(m0 + 4 * (lg + 16)) * DMODEL + lk;
    const float* pb0 = Wo + (size_t)(n0 + 4 * lg) * DMODEL + lk;
    const float* pb1 = Wo + (size_t)(n0 + 4 * (lg + 16)) * DMODEL + lk;

    u64 accp[8][4];
#pragma unroll
    for (int i = 0; i < 8; ++i)
#pragma unroll
        for (int jp = 0; jp < 4; ++jp) accp[i][jp] = 0ull;

    float4 ra[2], rb[2];
    ra[0].x = pa0[0]; ra[0].y = pa0[DMODEL]; ra[0].z = pa0[2 * DMODEL]; ra[0].w = pa0[3 * DMODEL];
    ra[1].x = pa1[0]; ra[1].y = pa1[DMODEL]; ra[1].z = pa1[2 * DMODEL]; ra[1].w = pa1[3 * DMODEL];
    rb[0].x = pb0[0]; rb[0].y = pb0[DMODEL]; rb[0].z = pb0[2 * DMODEL]; rb[0].w = pb0[3 * DMODEL];
    rb[1].x = pb1[0]; rb[1].y = pb1[DMODEL]; rb[1].z = pb1[2 * DMODEL]; rb[1].w = pb1[3 * DMODEL];
    *(float4*)&As[0][lk * 132 + 4 * lg]        = ra[0];
    *(float4*)&As[0][lk * 132 + 4 * (lg + 16)] = ra[1];
    *(float4*)&Bs[0][lk * 132 + 4 * lg]        = rb[0];
    *(float4*)&Bs[0][lk * 132 + 4 * (lg + 16)] = rb[1];
    __syncthreads();

    for (int kt = 0; kt < DMODEL; kt += 16) {
        const int cur = (kt >> 4) & 1;
        const bool more = (kt + 16) < DMODEL;
        if (more) {
            const float* qa0 = pa0 + kt + 16;
            const float* qa1 = pa1 + kt + 16;
            const float* qb0 = pb0 + kt + 16;
            const float* qb1 = pb1 + kt + 16;
            ra[0].x = qa0[0]; ra[0].y = qa0[DMODEL]; ra[0].z = qa0[2 * DMODEL]; ra[0].w = qa0[3 * DMODEL];
            ra[1].x = qa1[0]; ra[1].y = qa1[DMODEL]; ra[1].z = qa1[2 * DMODEL]; ra[1].w = qa1[3 * DMODEL];
            rb[0].x = qb0[0]; rb[0].y = qb0[DMODEL]; rb[0].z = qb0[2 * DMODEL]; rb[0].w = qb0[3 * DMODEL];
            rb[1].x = qb1[0]; rb[1].y = qb1[DMODEL]; rb[1].z = qb1[2 * DMODEL]; rb[1].w = qb1[3 * DMODEL];
        }
#pragma unroll
        for (int k = 0; k < 16; ++k) {
            float4 a0 = *(const float4*)&As[cur][k * 132 + 8 * ty];
            float4 a1 = *(const float4*)&As[cur][k * 132 + 8 * ty + 4];
            float4 b0 = *(const float4*)&Bs[cur][k * 132 + 4 * tx];
            float4 b1 = *(const float4*)&Bs[cur][k * 132 + 64 + 4 * tx];
            u64 bp[4];
            bp[0] = pack2(b0.x, b0.y); bp[1] = pack2(b0.z, b0.w);
            bp[2] = pack2(b1.x, b1.y); bp[3] = pack2(b1.z, b1.w);
            float aa[8] = {a0.x, a0.y, a0.z, a0.w, a1.x, a1.y, a1.z, a1.w};
#pragma unroll
            for (int i = 0; i < 8; ++i) {
                u64 ad = dup2(aa[i]);
                ffma2(accp[i][0], ad, bp[0]);
                ffma2(accp[i][1], ad, bp[1]);
                ffma2(accp[i][2], ad, bp[2]);
                ffma2(accp[i][3], ad, bp[3]);
            }
        }
        if (more) {
            const int nxt = cur ^ 1;
            *(float4*)&As[nxt][lk * 132 + 4 * lg]        = ra[0];
            *(float4*)&As[nxt][lk * 132 + 4 * (lg + 16)] = ra[1];
            *(float4*)&Bs[nxt][lk * 132 + 4 * lg]        = rb[0];
            *(float4*)&Bs[nxt][lk * 132 + 4 * (lg + 16)] = rb[1];
            __syncthreads();
        }
    }

#pragma unroll
    for (int g = 0; g < 2; ++g)
#pragma unroll
        for (int i = 0; i < 8; ++i) {
            int m = m0 + 8 * ty + i;
            float2 f0 = unpack2(accp[i][2 * g]);
            float2 f1 = unpack2(accp[i][2 * g + 1]);
            float4 o = make_float4(f0.x, f0.y, f1.x, f1.y);
            *(float4*)&out[(size_t)m * DMODEL + n0 + 64 * g + 4 * tx] = o;
        }
}

// ---------------------------------------------------------------------------
extern "C" void kernel_launch(void* const* d_in, const int* in_sizes, int n_in,
                              void* d_out, int out_size)
{
    const float* x  = (const float*)d_in[0];
    const float* Wq = (const float*)d_in[1];
    const float* Wk = (const float*)d_in[2];
    const float* Wv = (const float*)d_in[3];
    const float* Wo = (const float*)d_in[4];
    float* out = (float*)d_out;

    cudaFuncSetAttribute(attn_kernel,
                         cudaFuncAttributeMaxDynamicSharedMemorySize, ATTN_SMEM);

    dim3 gp(MTOT / 128, DMODEL / 128, 3);
    qkv_proj_kernel<<<gp, 256>>>(x, Wq, Wk, Wv);

    dim3 ga(SLEN / 128, BNUM * NH);
    attn_kernel<<<ga, 256, ATTN_SMEM>>>();

    dim3 go(MTOT / 128, DMODEL / 128);
    out_proj_kernel<<<go, 256>>>(Wo, out);
}